// round 5
// baseline (speedup 1.0000x reference)
#include <cuda_runtime.h>
#include <math.h>

#define SIZE 512
#define NB   16
#define NSEG 10
#define NBLK 512
#define NTHR 256
#define WPB  8
// Work unit: 128x8 pixel group = 4 x-adjacent 32x8 strips.
// 16 batches * 64 ybands * 4 xgroups = 4096 groups = exactly one per warp.

__global__ __launch_bounds__(NTHR) void bez_render(
    const float* __restrict__ traj,   // (16,2,4)
    const float* __restrict__ thin,   // (16,1,4)
    float* __restrict__ out)          // (16,512,512)
{
    __shared__ float    sW[40];           // bezier weights [k][p]
    __shared__ float    straj[NB * 8];
    __shared__ float    sthin[NB * 4];
    __shared__ float4   sp4[NB][NSEG];    // vy,vx,dy,dx
    __shared__ float    sinv[NB][NSEG];   // 1/(d2+1e-5)
    __shared__ float4   sab[NB][NSEG];    // ylo,yhi,xlo,xhi (thick-expanded)
    __shared__ float2   sthk[NB];         // thick, 1/thick
    __shared__ unsigned sxm[NB][64];      // per-(batch,yband) 16-bit x-strip mask

    int tid = threadIdx.x;

    // ---- Setup phase 1: stage inputs, weights, zero the activity table ----
    if (tid < 128) {
        straj[tid] = traj[tid];
    } else if (tid < 192) {
        sthin[tid - 128] = thin[tid - 128];
    } else if (tid < 232) {
        int i = tid - 192;
        int k = i / 10, p = i % 10;
        const int starts[4] = {10, 6, 3, 0};
        float n = (float)(starts[k] + p) - 9.5f;
        sW[i] = 0.75f * __expf(-0.125f * n * n);
    }
    #pragma unroll
    for (int i = 0; i < 4; i++) ((unsigned*)sxm)[tid + i * 256] = 0u;
    __syncthreads();

    // ---- Setup phase 2: 160 threads build segments + scatter strip masks ----
    if (tid < NB * NSEG) {
        int b = tid / NSEG;
        int s = tid % NSEG;
        const float* cy = straj + b * 8;
        const float* cx = straj + b * 8 + 4;

        float pt[2][2];
        #pragma unroll
        for (int e = 0; e < 2; e++) {
            int p = s + e;
            if (p < 10) {
                float sy = 0.f, sx = 0.f;
                #pragma unroll
                for (int k = 0; k < 4; k++) {
                    float w = sW[k * 10 + p];
                    sy = fmaf(cy[k], w, sy);
                    sx = fmaf(cx[k], w, sx);
                }
                pt[e][0] = sy * 512.0f;
                pt[e][1] = sx * 512.0f;
            } else {
                pt[e][0] = cy[3] * 512.0f;
                pt[e][1] = cx[3] * 512.0f;
            }
        }
        float vy = pt[0][0], vx = pt[0][1];
        float wy = pt[1][0], wx = pt[1][1];
        float dy = wy - vy, dx = wx - vx;

        float th = 0.f;
        #pragma unroll
        for (int k = 0; k < 4; k++) th += sthin[b * 4 + k] * 2.0f + 0.5f;
        float thick = 2.0f * th;

        float ylo = fminf(vy, wy) - thick, yhi = fmaxf(vy, wy) + thick;
        float xlo = fminf(vx, wx) - thick, xhi = fmaxf(vx, wx) + thick;

        sp4[b][s]  = make_float4(vy, vx, dy, dx);
        sinv[b][s] = 1.0f / (dy * dy + dx * dx + 1e-5f);
        sab[b][s]  = make_float4(ylo, yhi, xlo, xhi);
        if (s == 0) sthk[b] = make_float2(thick, 1.0f / thick);

        // Exact strip-index rectangle covered by this AABB.
        int yb0 = max(0,  (int)floorf(ylo * 0.125f));
        int yb1 = min(63, (int)floorf(yhi * 0.125f));
        int xs0 = max(0,  (int)floorf(xlo * 0.03125f));
        int xs1 = min(15, (int)floorf(xhi * 0.03125f));
        if (yb1 >= yb0 && xs1 >= xs0) {
            unsigned bits = ((1u << (xs1 - xs0 + 1)) - 1u) << xs0;
            for (int yb = yb0; yb <= yb1; yb++)
                atomicOr(&sxm[b][yb], bits);
        }
    }
    __syncthreads();

    // ---- Main: one 128x8 group per warp, no barriers ----
    int wid  = tid >> 5;
    int lane = tid & 31;
    int gid  = blockIdx.x * WPB + wid;       // 0..4095
    int b     = gid >> 8;
    int yband = (gid >> 2) & 63;
    int xg    = gid & 3;
    int y0    = yband << 3;

    float* op = out + ((size_t)b << 18) + (size_t)y0 * SIZE + (xg << 7);
    unsigned xm = (sxm[b][yband] >> (xg * 4)) & 0xFu;

    if (xm == 0) {
        // Entire 128x8 group is zero: 8 rows x 32 float4 (one per lane per row).
        float4 z = make_float4(0.f, 0.f, 0.f, 0.f);
        #pragma unroll
        for (int j = 0; j < 8; j++)
            *(float4*)(op + j * SIZE + lane * 4) = z;
        return;
    }

    float y0f = (float)y0;
    float2 tk = sthk[b];

    #pragma unroll
    for (int s4 = 0; s4 < 4; s4++) {
        float* ops = op + s4 * 32;
        unsigned m = 0;
        if ((xm >> s4) & 1u) {
            float x0f = (float)((xg << 7) + (s4 << 5));
            bool act = false;
            if (lane < NSEG) {
                float4 ab = sab[b][lane];
                act = (ab.y >= y0f) && (ab.x <= y0f + 7.f) &&
                      (ab.w >= x0f) && (ab.z <= x0f + 31.f);
            }
            m = __ballot_sync(0xffffffffu, act);
        }

        if (m == 0) {
            // Zero strip: 8 rows x 8 float4, 2 per lane.
            float4 z = make_float4(0.f, 0.f, 0.f, 0.f);
            int r0 = lane >> 3, c0 = lane & 7;
            *(float4*)(ops + r0 * SIZE + c0 * 4)       = z;
            *(float4*)(ops + (r0 + 4) * SIZE + c0 * 4) = z;
            continue;
        }

        float x = (float)((xg << 7) + (s4 << 5) + lane);
        float dmin[8];
        #pragma unroll
        for (int j = 0; j < 8; j++) dmin[j] = 3.0e38f;

        while (m) {
            int s = __ffs(m) - 1;
            m &= m - 1;
            float4 p4 = sp4[b][s];
            float  iv = sinv[b][s];
            float vy = p4.x, vx = p4.y, dy = p4.z, dx = p4.w;

            float pvx  = x - vx;
            float pxdx = pvx * dx;
            float pvy0 = y0f - vy;

            #pragma unroll
            for (int j = 0; j < 8; j++) {
                float pvy = pvy0 + (float)j;
                float dot = fmaf(pvy, dy, pxdx);
                float t   = __saturatef(dot * iv);
                float ry  = fmaf(-t, dy, pvy);
                float rx  = fmaf(-t, dx, pvx);
                float dd  = fmaf(ry, ry, rx * rx);
                dmin[j]   = fminf(dmin[j], dd);
            }
        }

        #pragma unroll
        for (int j = 0; j < 8; j++) {
            float dist = sqrtf(dmin[j]);
            float dark = __saturatef((tk.x - dist) * tk.y);
            ops[j * SIZE + lane] = dark;
        }
    }
}

extern "C" void kernel_launch(void* const* d_in, const int* in_sizes, int n_in,
                              void* d_out, int out_size) {
    const float* traj = (const float*)d_in[0];
    const float* thin = (const float*)d_in[1];
    float* out = (float*)d_out;

    bez_render<<<NBLK, NTHR>>>(traj, thin, out);
}